// round 5
// baseline (speedup 1.0000x reference)
#include <cuda_runtime.h>
#include <cstdint>

#define NN 100000
#define EE 1600000
#define FD 128
#define GG 512
#define LL 3
#define TG 64
#define NB ((NN + 1023) / 1024)   /* 98 scan blocks */
#define MTILES ((NN + 127) / 128) /* 782 */

#define BK 32                      /* K-chunk */
#define PIT 36                     /* chunk pitch: bank(m,k)=(4m+k)%32, conflict-free frags */
#define TPIT 132                   /* full-K pitch for T tile, same bank property */
#define ABUF (128 * PIT)           /* 4608 floats per chunk operand */
#define BUFSZ (2 * ABUF)           /* stage-1 A+W chunk = 9216 floats */
#define R0FLOATS (2 * BUFSZ)       /* 18432 floats: stage-1 double buffer / T tile (16896) */
#define W2SLOT ABUF                /* 4608 floats per W2 chunk slot */
#define FUSED_SMEM ((R0FLOATS + 2 * W2SLOT) * 4)  /* 110592 B */
#define PROJ_SMEM (2 * BUFSZ * 4)  /* 73728 B */

// ---------------- device scratch (no allocs allowed) ----------------
__device__ float g_h[(size_t)NN * FD];
__device__ float g_aggr[(size_t)NN * FD];
__device__ float g_t[(size_t)NN * FD];
__device__ float g_wt[9 * FD * FD];     // pre-transposed weights [n][k], tf32-rounded
__device__ int   g_deg[NN];
__device__ int   g_rowptr[NN + 1];
__device__ int   g_cursor[NN];
__device__ int   g_bsum[NB];
__device__ int   g_boff[NB];
__device__ int   g_srcsorted[EE];
__device__ int   g_gstart[GG + 1];

__device__ __forceinline__ uint32_t smem_u32(const void* p) {
    uint32_t a;
    asm("{ .reg .u64 t; cvta.to.shared.u64 t, %1; cvt.u32.u64 %0, t; }" : "=r"(a) : "l"(p));
    return a;
}
__device__ __forceinline__ void cp16(uint32_t dst, const void* src, int sz) {
    asm volatile("cp.async.cg.shared.global [%0], [%1], 16, %2;"
                 :: "r"(dst), "l"(src), "r"(sz) : "memory");
}
__device__ __forceinline__ float f2tf32f(float f) {
    uint32_t r;
    asm("cvt.rna.tf32.f32 %0, %1;" : "=r"(r) : "f"(f));
    return __uint_as_float(r);
}
__device__ __forceinline__ void mma_tf32(float* c, const uint32_t* a, const uint32_t* b) {
    asm volatile(
        "mma.sync.aligned.m16n8k8.row.col.f32.tf32.tf32.f32 "
        "{%0,%1,%2,%3}, {%4,%5,%6,%7}, {%8,%9}, {%0,%1,%2,%3};"
        : "+f"(c[0]), "+f"(c[1]), "+f"(c[2]), "+f"(c[3])
        : "r"(a[0]), "r"(a[1]), "r"(a[2]), "r"(a[3]), "r"(b[0]), "r"(b[1]));
}

// ---------------- CSR build ----------------
__global__ void k_zero_deg() {
    int i = blockIdx.x * 256 + threadIdx.x;
    if (i < NN) g_deg[i] = 0;
}
__global__ void k_hist(const int* __restrict__ dst) {
    int e = blockIdx.x * 256 + threadIdx.x;
    if (e < EE) atomicAdd(&g_deg[dst[e]], 1);
}
__global__ void k_scan1() {
    __shared__ int sh[1024];
    int i = blockIdx.x * 1024 + threadIdx.x;
    int v = (i < NN) ? g_deg[i] : 0;
    sh[threadIdx.x] = v;
    __syncthreads();
    for (int off = 1; off < 1024; off <<= 1) {
        int t = sh[threadIdx.x];
        int a = (threadIdx.x >= off) ? sh[threadIdx.x - off] : 0;
        __syncthreads();
        sh[threadIdx.x] = t + a;
        __syncthreads();
    }
    if (i < NN) g_rowptr[i + 1] = sh[threadIdx.x];
    if (threadIdx.x == 1023) g_bsum[blockIdx.x] = sh[1023];
}
__global__ void k_scan2() {
    __shared__ int sh[128];
    int t = threadIdx.x;
    int v = (t < NB) ? g_bsum[t] : 0;
    sh[t] = v;
    __syncthreads();
    for (int off = 1; off < 128; off <<= 1) {
        int x = sh[t];
        int a = (t >= off) ? sh[t - off] : 0;
        __syncthreads();
        sh[t] = x + a;
        __syncthreads();
    }
    if (t < NB) g_boff[t] = sh[t] - v;
}
__global__ void k_scan3() {
    int i = blockIdx.x * 1024 + threadIdx.x;
    if (i < NN) g_rowptr[i + 1] += g_boff[blockIdx.x];
    if (i == 0) g_rowptr[0] = 0;
}
__global__ void k_copycur() {
    int i = blockIdx.x * 256 + threadIdx.x;
    if (i < NN) g_cursor[i] = g_rowptr[i];
}
__global__ void k_bucket(const int* __restrict__ src, const int* __restrict__ dst) {
    int e = blockIdx.x * 256 + threadIdx.x;
    if (e < EE) {
        int d = dst[e];
        int pos = atomicAdd(&g_cursor[d], 1);
        g_srcsorted[pos] = src[e];
    }
}
__global__ void k_gstart(const int* __restrict__ batch) {
    int g = blockIdx.x * 256 + threadIdx.x;
    if (g <= GG) {
        int lo = 0, hi = NN;
        while (lo < hi) {
            int mid = (lo + hi) >> 1;
            if (batch[mid] < g) lo = mid + 1; else hi = mid;
        }
        g_gstart[g] = lo;
    }
}

// ---------------- weight transpose + tf32 rna rounding ----------------
__global__ void k_wtrans(const float* __restrict__ w1, const float* __restrict__ w2,
                         const float* __restrict__ w3) {
    __shared__ float t[32][33];
    int mi = blockIdx.z;
    const float* src = (mi < 3) ? (w1 + (size_t)mi * FD * FD)
                     : (mi < 6) ? (w2 + (size_t)(mi - 3) * FD * FD)
                                : (w3 + (size_t)(mi - 6) * FD * FD);
    float* dst = g_wt + (size_t)mi * FD * FD;
    int x0 = blockIdx.x * 32, y0 = blockIdx.y * 32;
    for (int dy = threadIdx.y; dy < 32; dy += 8)
        t[dy][threadIdx.x] = src[(size_t)(y0 + dy) * FD + x0 + threadIdx.x];
    __syncthreads();
    for (int dy = threadIdx.y; dy < 32; dy += 8)
        dst[(size_t)(x0 + dy) * FD + y0 + threadIdx.x] = f2tf32f(t[threadIdx.x][dy]);
}

// ---------------- aggregation + GIN combine, output tf32-rounded ----------------
__global__ void __launch_bounds__(256) k_aggr(const float* __restrict__ h,
                                              const float* __restrict__ epsp) {
    int node = blockIdx.x * 8 + (threadIdx.x >> 5);
    if (node >= NN) return;
    int lane = threadIdx.x & 31;
    int s = g_rowptr[node], e = g_rowptr[node + 1];
    float alpha = 1.0f + epsp[0];
    const float4* hp = (const float4*)h;
    float4 hv = hp[(size_t)node * 32 + lane];
    float4 acc = make_float4(alpha * hv.x, alpha * hv.y, alpha * hv.z, alpha * hv.w);
    int i = s;
    for (; i + 1 < e; i += 2) {
        int s0 = g_srcsorted[i], s1 = g_srcsorted[i + 1];
        float4 v0 = hp[(size_t)s0 * 32 + lane];
        float4 v1 = hp[(size_t)s1 * 32 + lane];
        acc.x += v0.x + v1.x; acc.y += v0.y + v1.y;
        acc.z += v0.z + v1.z; acc.w += v0.w + v1.w;
    }
    if (i < e) {
        int s0 = g_srcsorted[i];
        float4 v0 = hp[(size_t)s0 * 32 + lane];
        acc.x += v0.x; acc.y += v0.y; acc.z += v0.z; acc.w += v0.w;
    }
    acc.x = f2tf32f(acc.x); acc.y = f2tf32f(acc.y);
    acc.z = f2tf32f(acc.z); acc.w = f2tf32f(acc.w);
    ((float4*)g_aggr)[(size_t)node * 32 + lane] = acc;
}

// ---------------- fused GIN MLP: H = relu(A@W1t^T + b1) @ W2t^T + b2 ----------------
// A, W1t, W2t all tf32-pre-rounded. T tile held in SMEM between the two MMA chains.
__global__ void __launch_bounds__(256) k_gin_mlp(
    const float* __restrict__ A,
    const float* __restrict__ W1t, const float* __restrict__ b1p,
    const float* __restrict__ W2t, const float* __restrict__ b2p,
    float* __restrict__ C, int M)
{
    extern __shared__ float smem[];
    uint32_t sb = smem_u32(smem);
    float* w2s = smem + R0FLOATS;          // 2 slots of W2SLOT floats
    uint32_t w2b = sb + R0FLOATS * 4;

    int tid = threadIdx.x;
    int w = tid >> 5, lane = tid & 31;
    int m0 = blockIdx.x * 128;

    // stage1 chunk: A + W1 (2048 x 16B)
    auto stage1 = [&](int c, int buf) {
        uint32_t base = sb + (uint32_t)buf * (BUFSZ * 4);
#pragma unroll
        for (int i = 0; i < 8; i++) {
            int o = i * 256 + tid;
            int row = (o & 1023) >> 3;
            int q = o & 7;
            uint32_t dst = base + (uint32_t)((o >> 10) * (ABUF * 4) + row * (PIT * 4) + q * 16);
            if (o < 1024) {
                int m = m0 + row;
                const float* src = A + ((m < M) ? ((size_t)m * FD + c * BK + q * 4) : 0);
                cp16(dst, src, (m < M) ? 16 : 0);
            } else {
                cp16(dst, W1t + (size_t)row * FD + c * BK + q * 4, 16);
            }
        }
        asm volatile("cp.async.commit_group;" ::: "memory");
    };
    // W2 chunk: 1024 x 16B
    auto stageW2 = [&](int c, int slot) {
#pragma unroll
        for (int i = 0; i < 4; i++) {
            int o = i * 256 + tid;
            int row = o >> 3;
            int q = o & 7;
            uint32_t dst = w2b + (uint32_t)(slot * (W2SLOT * 4) + row * (PIT * 4) + q * 16);
            cp16(dst, W2t + (size_t)row * FD + c * BK + q * 4, 16);
        }
        asm volatile("cp.async.commit_group;" ::: "memory");
    };

    stage1(0, 0);        // g0
    stageW2(0, 0);       // g1
    stageW2(1, 1);       // g2

    int warpM = w >> 2, warpN = w & 3;
    int g = lane >> 2, t = lane & 3;

    float c[4][4][4];
#pragma unroll
    for (int ma = 0; ma < 4; ma++)
#pragma unroll
        for (int nb = 0; nb < 4; nb++)
#pragma unroll
            for (int r = 0; r < 4; r++) c[ma][nb][r] = 0.f;

    // ---- stage 1 mainloop: T_acc = A @ W1^T ----
#pragma unroll
    for (int ch = 0; ch < 4; ch++) {
        if (ch == 0) { stage1(1, 1); asm volatile("cp.async.wait_group 3;" ::: "memory"); }
        else if (ch == 1) { stage1(2, 0); asm volatile("cp.async.wait_group 1;" ::: "memory"); }
        else if (ch == 2) { stage1(3, 1); asm volatile("cp.async.wait_group 1;" ::: "memory"); }
        else { asm volatile("cp.async.wait_group 0;" ::: "memory"); }
        __syncthreads();

        const uint32_t* As = (const uint32_t*)(smem + (ch & 1) * BUFSZ);
        const uint32_t* Bs = As + ABUF;
#pragma unroll
        for (int ks = 0; ks < 4; ks++) {
            int k0 = ks * 8;
            uint32_t af[4][4];
#pragma unroll
            for (int ma = 0; ma < 4; ma++) {
                int r = warpM * 64 + ma * 16 + g;
                const uint32_t* ap = As + r * PIT + k0 + t;
                af[ma][0] = ap[0];
                af[ma][1] = ap[8 * PIT];
                af[ma][2] = ap[4];
                af[ma][3] = ap[8 * PIT + 4];
            }
            uint32_t bf[4][2];
#pragma unroll
            for (int nb = 0; nb < 4; nb++) {
                int n = warpN * 32 + nb * 8 + g;
                const uint32_t* bp = Bs + n * PIT + k0 + t;
                bf[nb][0] = bp[0];
                bf[nb][1] = bp[4];
            }
#pragma unroll
            for (int ma = 0; ma < 4; ma++)
#pragma unroll
                for (int nb = 0; nb < 4; nb++)
                    mma_tf32(c[ma][nb], af[ma], bf[nb]);
        }
        __syncthreads();
    }

    // ---- T = rna(relu(T_acc + b1)) into SMEM region0, [m][TPIT] ----
#pragma unroll
    for (int ma = 0; ma < 4; ma++) {
        int r0 = warpM * 64 + ma * 16 + g;
#pragma unroll
        for (int nb = 0; nb < 4; nb++) {
            int cn = warpN * 32 + nb * 8 + 2 * t;
            float b0 = b1p[cn], b1v = b1p[cn + 1];
            smem[r0 * TPIT + cn]           = f2tf32f(fmaxf(c[ma][nb][0] + b0, 0.f));
            smem[r0 * TPIT + cn + 1]       = f2tf32f(fmaxf(c[ma][nb][1] + b1v, 0.f));
            smem[(r0 + 8) * TPIT + cn]     = f2tf32f(fmaxf(c[ma][nb][2] + b0, 0.f));
            smem[(r0 + 8) * TPIT + cn + 1] = f2tf32f(fmaxf(c[ma][nb][3] + b1v, 0.f));
#pragma unroll
            for (int r = 0; r < 4; r++) c[ma][nb][r] = 0.f;
        }
    }
    __syncthreads();

    // ---- stage 2 mainloop: H_acc = T @ W2^T ----
    const uint32_t* Ts = (const uint32_t*)smem;
#pragma unroll
    for (int ch = 0; ch < 4; ch++) {
        if (ch == 2) asm volatile("cp.async.wait_group 1;" ::: "memory");  // W2 c2 (g6)
        else if (ch == 3) asm volatile("cp.async.wait_group 0;" ::: "memory");  // c3 (g7)
        if (ch >= 2) __syncthreads();

        const uint32_t* Bs = (const uint32_t*)(w2s + (ch & 1) * W2SLOT);
#pragma unroll
        for (int ks = 0; ks < 4; ks++) {
            int k0 = ch * 32 + ks * 8;
            uint32_t af[4][4];
#pragma unroll
            for (int ma = 0; ma < 4; ma++) {
                int r = warpM * 64 + ma * 16 + g;
                const uint32_t* ap = Ts + r * TPIT + k0 + t;
                af[ma][0] = ap[0];
                af[ma][1] = ap[8 * TPIT];
                af[ma][2] = ap[4];
                af[ma][3] = ap[8 * TPIT + 4];
            }
            uint32_t bf[4][2];
#pragma unroll
            for (int nb = 0; nb < 4; nb++) {
                int n = warpN * 32 + nb * 8 + g;
                const uint32_t* bp = Bs + n * PIT + ks * 8 + t;
                bf[nb][0] = bp[0];
                bf[nb][1] = bp[4];
            }
#pragma unroll
            for (int ma = 0; ma < 4; ma++)
#pragma unroll
                for (int nb = 0; nb < 4; nb++)
                    mma_tf32(c[ma][nb], af[ma], bf[nb]);
        }
        if (ch < 2) {
            __syncthreads();
            stageW2(ch + 2, ch & 1);   // g6, g7
        }
    }

    // ---- epilogue: H = acc + b2 (raw fp32; gnorm rounds later) ----
#pragma unroll
    for (int ma = 0; ma < 4; ma++) {
        int r0 = m0 + warpM * 64 + ma * 16 + g;
#pragma unroll
        for (int nb = 0; nb < 4; nb++) {
            int cn = warpN * 32 + nb * 8 + 2 * t;
            float b0 = b2p[cn], b1v = b2p[cn + 1];
            if (r0 < M)
                *(float2*)&C[(size_t)r0 * FD + cn] =
                    make_float2(c[ma][nb][0] + b0, c[ma][nb][1] + b1v);
            if (r0 + 8 < M)
                *(float2*)&C[(size_t)(r0 + 8) * FD + cn] =
                    make_float2(c[ma][nb][2] + b0, c[ma][nb][3] + b1v);
        }
    }
}

// ---------------- proj GEMM (single), cp.async pipelined ----------------
__global__ void __launch_bounds__(256) k_gemm_cp(
    const float* __restrict__ A,
    const float* __restrict__ Wt, const float* __restrict__ bias,
    float* __restrict__ C, int M, int relu)
{
    extern __shared__ float smem[];
    uint32_t sb = smem_u32(smem);

    int tid = threadIdx.x;
    int w = tid >> 5, lane = tid & 31;
    int m0 = blockIdx.x * 128;

    auto stage = [&](int c, int buf) {
        uint32_t base = sb + (uint32_t)buf * (BUFSZ * 4);
#pragma unroll
        for (int i = 0; i < 8; i++) {
            int o = i * 256 + tid;
            int row = (o & 1023) >> 3;
            int q = o & 7;
            uint32_t dst = base + (uint32_t)((o >> 10) * (ABUF * 4) + row * (PIT * 4) + q * 16);
            if (o < 1024) {
                int m = m0 + row;
                const float* src = A + ((m < M) ? ((size_t)m * FD + c * BK + q * 4) : 0);
                cp16(dst, src, (m < M) ? 16 : 0);
            } else {
                cp16(dst, Wt + (size_t)row * FD + c * BK + q * 4, 16);
            }
        }
        asm volatile("cp.async.commit_group;" ::: "memory");
    };

    stage(0, 0);

    int warpM = w >> 2, warpN = w & 3;
    int g = lane >> 2, t = lane & 3;

    float c[4][4][4];
#pragma unroll
    for (int ma = 0; ma < 4; ma++)
#pragma unroll
        for (int nb = 0; nb < 4; nb++)
#pragma unroll
            for (int r = 0; r < 4; r++) c[ma][nb][r] = 0.f;

#pragma unroll
    for (int ch = 0; ch < 4; ch++) {
        if (ch < 3) stage(ch + 1, (ch + 1) & 1);
        if (ch < 3)
            asm volatile("cp.async.wait_group 1;" ::: "memory");
        else
            asm volatile("cp.async.wait_group 0;" ::: "memory");
        __syncthreads();

        const uint32_t* As = (const uint32_t*)(smem + (ch & 1) * BUFSZ);
        const uint32_t* Bs = As + ABUF;
#pragma unroll
        for (int ks = 0; ks < 4; ks++) {
            int k0 = ks * 8;
            uint32_t af[4][4];
#pragma unroll
            for (int ma = 0; ma < 4; ma++) {
                int r = warpM * 64 + ma * 16 + g;
                const uint32_t* ap = As + r * PIT + k0 + t;
                af[ma][0] = ap[0];
                af[ma][1] = ap[8 * PIT];
                af[ma][2] = ap[4];
                af[ma][3] = ap[8 * PIT + 4];
            }
            uint32_t bf[4][2];
#pragma unroll
            for (int nb = 0; nb < 4; nb++) {
                int n = warpN * 32 + nb * 8 + g;
                const uint32_t* bp = Bs + n * PIT + k0 + t;
                bf[nb][0] = bp[0];
                bf[nb][1] = bp[4];
            }
#pragma unroll
            for (int ma = 0; ma < 4; ma++)
#pragma unroll
                for (int nb = 0; nb < 4; nb++)
                    mma_tf32(c[ma][nb], af[ma], bf[nb]);
        }
        __syncthreads();
    }

#pragma unroll
    for (int ma = 0; ma < 4; ma++) {
        int r0 = m0 + warpM * 64 + ma * 16 + g;
#pragma unroll
        for (int nb = 0; nb < 4; nb++) {
            int cn = warpN * 32 + nb * 8 + 2 * t;
            float b0 = bias[cn], b1 = bias[cn + 1];
            float o0 = c[ma][nb][0] + b0, o1 = c[ma][nb][1] + b1;
            float o2 = c[ma][nb][2] + b0, o3 = c[ma][nb][3] + b1;
            if (relu) {
                o0 = fmaxf(o0, 0.f); o1 = fmaxf(o1, 0.f);
                o2 = fmaxf(o2, 0.f); o3 = fmaxf(o3, 0.f);
            }
            if (r0 < M)     *(float2*)&C[(size_t)r0 * FD + cn]       = make_float2(o0, o1);
            if (r0 + 8 < M) *(float2*)&C[(size_t)(r0 + 8) * FD + cn] = make_float2(o2, o3);
        }
    }
}

// ---------------- GraphNorm (+relu), output tf32-rounded ----------------
__global__ void __launch_bounds__(128) k_gnorm(
    float* __restrict__ h,
    const float* __restrict__ scale, const float* __restrict__ weight,
    const float* __restrict__ bias)
{
    int g = blockIdx.x;
    int f = threadIdx.x;
    int s = g_gstart[g], e = g_gstart[g + 1];
    float cnt = fmaxf((float)(e - s), 1.0f);

    float sum = 0.f;
#pragma unroll 4
    for (int i = s; i < e; i++) sum += h[(size_t)i * FD + f];
    float ms = (sum / cnt) * scale[f];

    float v = 0.f;
#pragma unroll 4
    for (int i = s; i < e; i++) {
        float d = h[(size_t)i * FD + f] - ms;
        v += d * d;
    }
    float inv = weight[f] * rsqrtf(v / cnt + 1e-8f);
    float bf = bias[f];

#pragma unroll 4
    for (int i = s; i < e; i++) {
        float d = h[(size_t)i * FD + f] - ms;
        h[(size_t)i * FD + f] = f2tf32f(fmaxf(inv * d + bf, 0.f));
    }
}

// ---------------- pool + fused tiny GEMM ----------------
__global__ void __launch_bounds__(128) k_pool(
    const float* __restrict__ t,
    const float* __restrict__ w2, const float* __restrict__ b2,
    float* __restrict__ out, int lofs)
{
    __shared__ float sp[128];
    int g = blockIdx.x;
    int f = threadIdx.x;
    int s = g_gstart[g], e = g_gstart[g + 1];
    float acc = 0.f;
#pragma unroll 4
    for (int i = s; i < e; i++) acc += t[(size_t)i * FD + f];
    sp[f] = acc;
    __syncthreads();
    if (f < TG) {
        float o = (float)(e - s) * b2[f];
#pragma unroll 8
        for (int k = 0; k < FD; k++) o += sp[k] * w2[k * TG + f];
        out[(size_t)g * (LL * TG) + lofs + f] = o;
    }
}

// ---------------- launcher ----------------
extern "C" void kernel_launch(void* const* d_in, const int* in_sizes, int n_in,
                              void* d_out, int out_size) {
    const float* x        = (const float*)d_in[0];
    const int*   edge     = (const int*)d_in[1];
    const int*   batch    = (const int*)d_in[2];
    const float* conv_w1  = (const float*)d_in[3];
    const float* conv_b1  = (const float*)d_in[4];
    const float* conv_w2  = (const float*)d_in[5];
    const float* conv_b2  = (const float*)d_in[6];
    const float* eps      = (const float*)d_in[7];
    const float* gn_scale = (const float*)d_in[8];
    const float* gn_weight= (const float*)d_in[9];
    const float* gn_bias  = (const float*)d_in[10];
    const float* proj_w1  = (const float*)d_in[11];
    const float* proj_b1  = (const float*)d_in[12];
    const float* proj_w2  = (const float*)d_in[13];
    const float* proj_b2  = (const float*)d_in[14];
    float* out = (float*)d_out;

    const int* src = edge;
    const int* dst = edge + EE;

    float *p_h, *p_aggr, *p_t, *p_wt;
    cudaGetSymbolAddress((void**)&p_h, g_h);
    cudaGetSymbolAddress((void**)&p_aggr, g_aggr);
    cudaGetSymbolAddress((void**)&p_t, g_t);
    cudaGetSymbolAddress((void**)&p_wt, g_wt);

    cudaFuncSetAttribute(k_gin_mlp, cudaFuncAttributeMaxDynamicSharedMemorySize, FUSED_SMEM);
    cudaFuncSetAttribute(k_gemm_cp, cudaFuncAttributeMaxDynamicSharedMemorySize, PROJ_SMEM);

    // CSR build + graph starts + weight transpose (tf32-rounded)
    k_zero_deg<<<(NN + 255) / 256, 256>>>();
    k_hist<<<(EE + 255) / 256, 256>>>(dst);
    k_scan1<<<NB, 1024>>>();
    k_scan2<<<1, 128>>>();
    k_scan3<<<NB, 1024>>>();
    k_copycur<<<(NN + 255) / 256, 256>>>();
    k_bucket<<<(EE + 255) / 256, 256>>>(src, dst);
    k_gstart<<<3, 256>>>(batch);
    k_wtrans<<<dim3(4, 4, 9), dim3(32, 8)>>>(conv_w1, conv_w2, proj_w1);

    const float* h = x;
    for (int l = 0; l < LL; l++) {
        // aggr = rna((1+eps)h + sum_j h_j)
        k_aggr<<<(NN + 7) / 8, 256>>>(h, eps + l);
        // h = relu(aggr @ W1 + b1) @ W2 + b2   (fused, T in SMEM)
        k_gin_mlp<<<MTILES, 256, FUSED_SMEM>>>(p_aggr,
                                               p_wt + (size_t)l * FD * FD,
                                               conv_b1 + (size_t)l * FD,
                                               p_wt + (size_t)(3 + l) * FD * FD,
                                               conv_b2 + (size_t)l * FD, p_h, NN);
        // GraphNorm + relu + rna
        k_gnorm<<<GG, 128>>>(p_h, gn_scale + (size_t)l * FD,
                             gn_weight + (size_t)l * FD, gn_bias + (size_t)l * FD);
        // t = relu(h @ proj_w1 + b1)
        k_gemm_cp<<<MTILES, 256, PROJ_SMEM>>>(p_h,
                                              p_wt + (size_t)(6 + l) * FD * FD,
                                              proj_b1 + (size_t)l * FD, p_t, NN, 1);
        // pooled projection
        k_pool<<<GG, 128>>>(p_t, proj_w2 + (size_t)l * FD * TG,
                            proj_b2 + (size_t)l * TG, out, l * TG);
        h = p_h;
    }
}